// round 1
// baseline (speedup 1.0000x reference)
#include <cuda_runtime.h>

#define N_    1024
#define M_    1024
#define D_    128
#define NNZ_  32768
#define H_    256

// ---------------- device scratch (no allocations allowed) ----------------
__device__ int   g_cnt[M_];
__device__ int   g_off[M_];
__device__ int   g_cur[M_];
__device__ int   g_bucket[NNZ_];
__device__ __align__(16) float g_eX[M_ * D_];      // [m][d]
__device__ __align__(16) float g_hxT[H_ * N_];     // [h][n]
__device__ __align__(16) float g_hebT[H_ * M_];    // [h][m]  (includes +b1)

// ---------------- small helpers ----------------
__device__ __forceinline__ unsigned long long bcast2(float v) {
    unsigned long long r;
    asm("mov.b64 %0, {%1, %1};" : "=l"(r) : "f"(v));
    return r;
}

__device__ __forceinline__ float2 unpack2(unsigned long long v) {
    float lo, hi;
    asm("mov.b64 {%0, %1}, %2;" : "=f"(lo), "=f"(hi) : "l"(v));
    return make_float2(lo, hi);
}

// acc2 += relu(a2 + b2) * w2   (packed f32x2; relu on the scalar halves)
__device__ __forceinline__ void relu_fma2(unsigned long long &acc,
                                          unsigned long long a,
                                          unsigned long long b,
                                          unsigned long long w) {
    asm("{\n\t"
        ".reg .b64 t;\n\t"
        ".reg .f32 lo, hi;\n\t"
        "add.rn.f32x2 t, %1, %2;\n\t"
        "mov.b64 {lo, hi}, t;\n\t"
        "max.f32 lo, lo, 0f00000000;\n\t"
        "max.f32 hi, hi, 0f00000000;\n\t"
        "mov.b64 t, {lo, hi};\n\t"
        "fma.rn.f32x2 %0, t, %3, %0;\n\t"
        "}"
        : "+l"(acc) : "l"(a), "l"(b), "l"(w));
}

__device__ __forceinline__ float sigmoidf_fast(float x) {
    return 1.0f / (1.0f + __expf(-x));
}

// ---------------- stage 1: scatter-mean (CSR build) ----------------
__global__ void k_zero() {
    g_cnt[threadIdx.x] = 0;
}

__global__ void k_count(const int* __restrict__ E) {
    int j = blockIdx.x * blockDim.x + threadIdx.x;
    atomicAdd(&g_cnt[E[j]], 1);
}

__global__ void k_scan() {
    __shared__ int sh[M_];
    int t = threadIdx.x;
    int c = g_cnt[t];
    sh[t] = c;
    __syncthreads();
    for (int o = 1; o < M_; o <<= 1) {
        int v = (t >= o) ? sh[t - o] : 0;
        __syncthreads();
        sh[t] += v;
        __syncthreads();
    }
    int excl = sh[t] - c;   // exclusive prefix
    g_off[t] = excl;
    g_cur[t] = excl;
}

__global__ void k_bucket(const int* __restrict__ E, const int* __restrict__ V) {
    int j = blockIdx.x * blockDim.x + threadIdx.x;
    int pos = atomicAdd(&g_cur[E[j]], 1);
    g_bucket[pos] = V[j];
}

// eX[m][d] = mean of X[v][d] over bucket m   (1024 blocks x 128 threads)
__global__ void k_ex(const float* __restrict__ X) {
    int m = blockIdx.x;
    int d = threadIdx.x;
    int cnt   = g_cnt[m];
    int start = g_off[m];
    float acc = 0.f;
    for (int k = 0; k < cnt; ++k) {
        int v = g_bucket[start + k];
        acc += X[v * D_ + d];
    }
    float denom = (cnt > 0) ? (float)cnt : 1.0f;
    g_eX[m * D_ + d] = acc / denom;
}

// ---------------- stage 2: the two small GEMMs (fused, transposed output) --
// z==0: outT = (X @ W1[:D]).T            -> g_hxT[h][n]
// z==1: outT = (eX @ W1[D:]).T + b1      -> g_hebT[h][m]
__global__ __launch_bounds__(256) void k_gemm(const float* __restrict__ X,
                                              const float* __restrict__ W1,
                                              const float* __restrict__ b1) {
    int z = blockIdx.z;
    const float* A    = z ? g_eX   : X;
    float*       outT = z ? g_hebT : g_hxT;
    int dof = z ? D_ : 0;

    int n0 = blockIdx.x * 64;
    int h0 = blockIdx.y * 64;

    __shared__ float As[16][65];   // [dk][n]
    __shared__ float Ws[16][64];   // [dk][h]

    int tid = threadIdx.x;
    int tn  = tid & 15;   // n sub-tile (4 wide)
    int th  = tid >> 4;   // h sub-tile (4 wide)

    float acc[4][4];      // [n][h]
    #pragma unroll
    for (int i = 0; i < 4; i++)
        #pragma unroll
        for (int j = 0; j < 4; j++)
            acc[i][j] = z ? b1[h0 + th * 4 + j] : 0.f;

    for (int d0 = 0; d0 < D_; d0 += 16) {
        // load A chunk (16 x 64, transposed into [dk][n])
        #pragma unroll
        for (int r = 0; r < 4; r++) {
            int i  = r * 256 + tid;
            int dk = i & 15;
            int nl = i >> 4;
            As[dk][nl] = A[(n0 + nl) * D_ + d0 + dk];
        }
        // load W chunk (16 x 64)
        #pragma unroll
        for (int r = 0; r < 4; r++) {
            int i  = r * 256 + tid;
            int hh = i & 63;
            int dk = i >> 6;
            Ws[dk][hh] = W1[(dof + d0 + dk) * H_ + h0 + hh];
        }
        __syncthreads();
        #pragma unroll
        for (int dk = 0; dk < 16; dk++) {
            float a[4], w[4];
            #pragma unroll
            for (int i = 0; i < 4; i++) a[i] = As[dk][tn * 4 + i];
            #pragma unroll
            for (int j = 0; j < 4; j++) w[j] = Ws[dk][th * 4 + j];
            #pragma unroll
            for (int i = 0; i < 4; i++)
                #pragma unroll
                for (int j = 0; j < 4; j++)
                    acc[i][j] = fmaf(a[i], w[j], acc[i][j]);
        }
        __syncthreads();
    }

    // write transposed: outT[h][n], float4 over n
    #pragma unroll
    for (int j = 0; j < 4; j++) {
        int h = h0 + th * 4 + j;
        float4 v = make_float4(acc[0][j], acc[1][j], acc[2][j], acc[3][j]);
        *(float4*)&outT[h * N_ + n0 + tn * 4] = v;
    }
}

// ---------------- stage 3: main N x M x H contraction ----------------
// grid (M/64, N/64), 128 threads. Each thread: 8 n (4 f32x2 pairs) x 4 m.
__global__ __launch_bounds__(128) void k_main(const float* __restrict__ W2,
                                              const float* __restrict__ b2p,
                                              float* __restrict__ out) {
    __shared__ __align__(16) float hx_s[64][68];
    __shared__ __align__(16) float heb_s[64][68];
    __shared__ float w2_s[64];

    int m0  = blockIdx.x * 64;
    int n0  = blockIdx.y * 64;
    int tid = threadIdx.x;
    int tn  = tid & 7;    // n base = tn*8
    int tm  = tid >> 3;   // m base = tm*4   (0..15)

    unsigned long long acc[4][4];   // [mj][npair]
    #pragma unroll
    for (int j = 0; j < 4; j++)
        #pragma unroll
        for (int p = 0; p < 4; p++)
            acc[j][p] = 0ull;

    int cg = tid & 15;    // float4 column group for loads
    int r0 = tid >> 4;    // row base for loads

    for (int hc = 0; hc < 4; hc++) {
        int hb = hc * 64;
        // cooperative chunk load (coalesced rows, padded smem)
        #pragma unroll
        for (int k = 0; k < 8; k++) {
            int hh = k * 8 + r0;
            float4 a = *(const float4*)&g_hxT[(hb + hh) * N_ + n0 + cg * 4];
            *(float4*)&hx_s[hh][cg * 4] = a;
            float4 b = *(const float4*)&g_hebT[(hb + hh) * M_ + m0 + cg * 4];
            *(float4*)&heb_s[hh][cg * 4] = b;
        }
        if (tid < 64) w2_s[tid] = W2[hb + tid];
        __syncthreads();

        #pragma unroll 4
        for (int hh = 0; hh < 64; hh++) {
            ulonglong2 pa = *(const ulonglong2*)&hx_s[hh][tn * 8];
            ulonglong2 pb = *(const ulonglong2*)&hx_s[hh][tn * 8 + 4];
            float4 bm = *(const float4*)&heb_s[hh][tm * 4];
            unsigned long long w2p = bcast2(w2_s[hh]);
            unsigned long long q0 = bcast2(bm.x);
            unsigned long long q1 = bcast2(bm.y);
            unsigned long long q2 = bcast2(bm.z);
            unsigned long long q3 = bcast2(bm.w);

            relu_fma2(acc[0][0], pa.x, q0, w2p);
            relu_fma2(acc[0][1], pa.y, q0, w2p);
            relu_fma2(acc[0][2], pb.x, q0, w2p);
            relu_fma2(acc[0][3], pb.y, q0, w2p);

            relu_fma2(acc[1][0], pa.x, q1, w2p);
            relu_fma2(acc[1][1], pa.y, q1, w2p);
            relu_fma2(acc[1][2], pb.x, q1, w2p);
            relu_fma2(acc[1][3], pb.y, q1, w2p);

            relu_fma2(acc[2][0], pa.x, q2, w2p);
            relu_fma2(acc[2][1], pa.y, q2, w2p);
            relu_fma2(acc[2][2], pb.x, q2, w2p);
            relu_fma2(acc[2][3], pb.y, q2, w2p);

            relu_fma2(acc[3][0], pa.x, q3, w2p);
            relu_fma2(acc[3][1], pa.y, q3, w2p);
            relu_fma2(acc[3][2], pb.x, q3, w2p);
            relu_fma2(acc[3][3], pb.y, q3, w2p);
        }
        __syncthreads();
    }

    float b2v = b2p[0];
    // epilogue: sigmoid + store. Each npair p covers n = n0+tn*8+2p{+0,+1}
    #pragma unroll
    for (int p = 0; p < 4; p++) {
        float2 u[4];
        #pragma unroll
        for (int j = 0; j < 4; j++) u[j] = unpack2(acc[j][p]);
        {
            int n = n0 + tn * 8 + 2 * p;
            float4 o;
            o.x = sigmoidf_fast(u[0].x + b2v);
            o.y = sigmoidf_fast(u[1].x + b2v);
            o.z = sigmoidf_fast(u[2].x + b2v);
            o.w = sigmoidf_fast(u[3].x + b2v);
            *(float4*)&out[n * M_ + m0 + tm * 4] = o;
        }
        {
            int n = n0 + tn * 8 + 2 * p + 1;
            float4 o;
            o.x = sigmoidf_fast(u[0].y + b2v);
            o.y = sigmoidf_fast(u[1].y + b2v);
            o.z = sigmoidf_fast(u[2].y + b2v);
            o.w = sigmoidf_fast(u[3].y + b2v);
            *(float4*)&out[n * M_ + m0 + tm * 4] = o;
        }
    }
}

// ---------------- launch ----------------
extern "C" void kernel_launch(void* const* d_in, const int* in_sizes, int n_in,
                              void* d_out, int out_size) {
    const float* X  = (const float*)d_in[0];
    const int*   V  = (const int*)d_in[1];
    const int*   E  = (const int*)d_in[2];
    const float* W1 = (const float*)d_in[3];
    const float* b1 = (const float*)d_in[4];
    const float* W2 = (const float*)d_in[5];
    const float* b2 = (const float*)d_in[6];
    float* out = (float*)d_out;

    k_zero<<<1, M_>>>();
    k_count<<<NNZ_ / 256, 256>>>(E);
    k_scan<<<1, M_>>>();
    k_bucket<<<NNZ_ / 256, 256>>>(E, V);
    k_ex<<<M_, D_>>>(X);
    k_gemm<<<dim3(N_ / 64, H_ / 64, 2), 256>>>(X, W1, b1);
    k_main<<<dim3(M_ / 64, N_ / 64), 128>>>(W2, b2, out);
}

// round 2
// speedup vs baseline: 1.1787x; 1.1787x over previous
#include <cuda_runtime.h>

#define N_    1024
#define M_    1024
#define D_    128
#define NNZ_  32768
#define H_    256

// ---------------- device scratch (no allocations allowed) ----------------
__device__ int   g_cnt[M_];
__device__ __align__(16) float g_sum[M_ * D_];     // raw scatter sums [m][d]
__device__ __align__(16) float g_hxT[H_ * N_];     // [h][n]
__device__ __align__(16) float g_hebT[H_ * M_];    // [h][m]  (includes /cnt and +b1)

// ---------------- small helpers ----------------
__device__ __forceinline__ unsigned long long bcast2(float v) {
    unsigned long long r;
    asm("mov.b64 %0, {%1, %1};" : "=l"(r) : "f"(v));
    return r;
}

__device__ __forceinline__ float2 unpack2(unsigned long long v) {
    float lo, hi;
    asm("mov.b64 {%0, %1}, %2;" : "=f"(lo), "=f"(hi) : "l"(v));
    return make_float2(lo, hi);
}

// acc2 += relu(a2 + b2) * w2   (packed f32x2; relu on the scalar halves)
__device__ __forceinline__ void relu_fma2(unsigned long long &acc,
                                          unsigned long long a,
                                          unsigned long long b,
                                          unsigned long long w) {
    asm("{\n\t"
        ".reg .b64 t;\n\t"
        ".reg .f32 lo, hi;\n\t"
        "add.rn.f32x2 t, %1, %2;\n\t"
        "mov.b64 {lo, hi}, t;\n\t"
        "max.f32 lo, lo, 0f00000000;\n\t"
        "max.f32 hi, hi, 0f00000000;\n\t"
        "mov.b64 t, {lo, hi};\n\t"
        "fma.rn.f32x2 %0, t, %3, %0;\n\t"
        "}"
        : "+l"(acc) : "l"(a), "l"(b), "l"(w));
}

__device__ __forceinline__ float sigmoidf_fast(float x) {
    return 1.0f / (1.0f + __expf(-x));
}

// ---------------- stage 1: zero scratch ----------------
// grid 128 x 256 : 32768 float4 stores for g_sum, first 1024 threads zero g_cnt
__global__ void k_init() {
    int i = blockIdx.x * blockDim.x + threadIdx.x;
    ((float4*)g_sum)[i] = make_float4(0.f, 0.f, 0.f, 0.f);
    if (i < M_) g_cnt[i] = 0;
}

// ---------------- stage 2: vector-atomic scatter ----------------
// one warp per edge; each lane reduces a float4 of the X row into g_sum[e]
__global__ __launch_bounds__(256) void k_scatter(const float* __restrict__ X,
                                                 const int* __restrict__ V,
                                                 const int* __restrict__ E) {
    int edge = blockIdx.x * 8 + (threadIdx.x >> 5);
    int lane = threadIdx.x & 31;
    int e = E[edge];
    int v = V[edge];
    float4 x = *(const float4*)&X[v * D_ + lane * 4];
    float* dst = &g_sum[e * D_ + lane * 4];
    asm volatile("red.global.add.v4.f32 [%0], {%1, %2, %3, %4};"
                 :: "l"(dst), "f"(x.x), "f"(x.y), "f"(x.z), "f"(x.w) : "memory");
    if (lane == 0) atomicAdd(&g_cnt[e], 1);
}

// ---------------- stage 3: the two small GEMMs (fused, transposed output) --
// z==0: outT = (X @ W1[:D]).T                       -> g_hxT[h][n]
// z==1: outT = ((g_sum @ W1[D:]) * rcp_cnt).T + b1  -> g_hebT[h][m]
__global__ __launch_bounds__(256) void k_gemm(const float* __restrict__ X,
                                              const float* __restrict__ W1,
                                              const float* __restrict__ b1) {
    int z = blockIdx.z;
    const float* A    = z ? g_sum  : X;
    float*       outT = z ? g_hebT : g_hxT;
    int dof = z ? D_ : 0;

    int n0 = blockIdx.x * 64;
    int h0 = blockIdx.y * 64;

    __shared__ float As[16][65];   // [dk][n]
    __shared__ float Ws[16][64];   // [dk][h]

    int tid = threadIdx.x;
    int tn  = tid & 15;   // n sub-tile (4 wide)
    int th  = tid >> 4;   // h sub-tile (4 wide)

    float acc[4][4];      // [n][h]
    #pragma unroll
    for (int i = 0; i < 4; i++)
        #pragma unroll
        for (int j = 0; j < 4; j++)
            acc[i][j] = 0.f;

    for (int d0 = 0; d0 < D_; d0 += 16) {
        // load A chunk (16 x 64, transposed into [dk][n])
        #pragma unroll
        for (int r = 0; r < 4; r++) {
            int i  = r * 256 + tid;
            int dk = i & 15;
            int nl = i >> 4;
            As[dk][nl] = A[(n0 + nl) * D_ + d0 + dk];
        }
        // load W chunk (16 x 64)
        #pragma unroll
        for (int r = 0; r < 4; r++) {
            int i  = r * 256 + tid;
            int hh = i & 63;
            int dk = i >> 6;
            Ws[dk][hh] = W1[(dof + d0 + dk) * H_ + h0 + hh];
        }
        __syncthreads();
        #pragma unroll
        for (int dk = 0; dk < 16; dk++) {
            float a[4], w[4];
            #pragma unroll
            for (int i = 0; i < 4; i++) a[i] = As[dk][tn * 4 + i];
            #pragma unroll
            for (int j = 0; j < 4; j++) w[j] = Ws[dk][th * 4 + j];
            #pragma unroll
            for (int i = 0; i < 4; i++)
                #pragma unroll
                for (int j = 0; j < 4; j++)
                    acc[i][j] = fmaf(a[i], w[j], acc[i][j]);
        }
        __syncthreads();
    }

    // epilogue: for z==1 fold in the scatter-mean divide and +b1
    float scale[4] = {1.f, 1.f, 1.f, 1.f};
    if (z) {
        #pragma unroll
        for (int i = 0; i < 4; i++) {
            int c = g_cnt[n0 + tn * 4 + i];
            scale[i] = 1.0f / ((c > 0) ? (float)c : 1.0f);
        }
    }
    #pragma unroll
    for (int j = 0; j < 4; j++) {
        int h = h0 + th * 4 + j;
        float bb = z ? b1[h] : 0.f;
        float4 v = make_float4(acc[0][j] * scale[0] + bb,
                               acc[1][j] * scale[1] + bb,
                               acc[2][j] * scale[2] + bb,
                               acc[3][j] * scale[3] + bb);
        *(float4*)&outT[h * N_ + n0 + tn * 4] = v;
    }
}

// ---------------- stage 4: main N x M x H contraction ----------------
// grid (M/64, N/64), 128 threads. Each thread: 8 n (4 f32x2 pairs) x 4 m.
__global__ __launch_bounds__(128) void k_main(const float* __restrict__ W2,
                                              const float* __restrict__ b2p,
                                              float* __restrict__ out) {
    __shared__ __align__(16) float hx_s[64][68];
    __shared__ __align__(16) float heb_s[64][68];
    __shared__ float w2_s[64];

    int m0  = blockIdx.x * 64;
    int n0  = blockIdx.y * 64;
    int tid = threadIdx.x;
    int tn  = tid & 7;    // n base = tn*8
    int tm  = tid >> 3;   // m base = tm*4   (0..15)

    unsigned long long acc[4][4];   // [mj][npair]
    #pragma unroll
    for (int j = 0; j < 4; j++)
        #pragma unroll
        for (int p = 0; p < 4; p++)
            acc[j][p] = 0ull;

    int cg = tid & 15;    // float4 column group for loads
    int r0 = tid >> 4;    // row base for loads

    for (int hc = 0; hc < 4; hc++) {
        int hb = hc * 64;
        // cooperative chunk load (coalesced rows, padded smem)
        #pragma unroll
        for (int k = 0; k < 8; k++) {
            int hh = k * 8 + r0;
            float4 a = *(const float4*)&g_hxT[(hb + hh) * N_ + n0 + cg * 4];
            *(float4*)&hx_s[hh][cg * 4] = a;
            float4 b = *(const float4*)&g_hebT[(hb + hh) * M_ + m0 + cg * 4];
            *(float4*)&heb_s[hh][cg * 4] = b;
        }
        if (tid < 64) w2_s[tid] = W2[hb + tid];
        __syncthreads();

        #pragma unroll 4
        for (int hh = 0; hh < 64; hh++) {
            ulonglong2 pa = *(const ulonglong2*)&hx_s[hh][tn * 8];
            ulonglong2 pb = *(const ulonglong2*)&hx_s[hh][tn * 8 + 4];
            float4 bm = *(const float4*)&heb_s[hh][tm * 4];
            unsigned long long w2p = bcast2(w2_s[hh]);
            unsigned long long q0 = bcast2(bm.x);
            unsigned long long q1 = bcast2(bm.y);
            unsigned long long q2 = bcast2(bm.z);
            unsigned long long q3 = bcast2(bm.w);

            relu_fma2(acc[0][0], pa.x, q0, w2p);
            relu_fma2(acc[0][1], pa.y, q0, w2p);
            relu_fma2(acc[0][2], pb.x, q0, w2p);
            relu_fma2(acc[0][3], pb.y, q0, w2p);

            relu_fma2(acc[1][0], pa.x, q1, w2p);
            relu_fma2(acc[1][1], pa.y, q1, w2p);
            relu_fma2(acc[1][2], pb.x, q1, w2p);
            relu_fma2(acc[1][3], pb.y, q1, w2p);

            relu_fma2(acc[2][0], pa.x, q2, w2p);
            relu_fma2(acc[2][1], pa.y, q2, w2p);
            relu_fma2(acc[2][2], pb.x, q2, w2p);
            relu_fma2(acc[2][3], pb.y, q2, w2p);

            relu_fma2(acc[3][0], pa.x, q3, w2p);
            relu_fma2(acc[3][1], pa.y, q3, w2p);
            relu_fma2(acc[3][2], pb.x, q3, w2p);
            relu_fma2(acc[3][3], pb.y, q3, w2p);
        }
        __syncthreads();
    }

    float b2v = b2p[0];
    // epilogue: sigmoid + store. Each npair p covers n = n0+tn*8+2p{+0,+1}
    #pragma unroll
    for (int p = 0; p < 4; p++) {
        float2 u[4];
        #pragma unroll
        for (int j = 0; j < 4; j++) u[j] = unpack2(acc[j][p]);
        {
            int n = n0 + tn * 8 + 2 * p;
            float4 o;
            o.x = sigmoidf_fast(u[0].x + b2v);
            o.y = sigmoidf_fast(u[1].x + b2v);
            o.z = sigmoidf_fast(u[2].x + b2v);
            o.w = sigmoidf_fast(u[3].x + b2v);
            *(float4*)&out[n * M_ + m0 + tm * 4] = o;
        }
        {
            int n = n0 + tn * 8 + 2 * p + 1;
            float4 o;
            o.x = sigmoidf_fast(u[0].y + b2v);
            o.y = sigmoidf_fast(u[1].y + b2v);
            o.z = sigmoidf_fast(u[2].y + b2v);
            o.w = sigmoidf_fast(u[3].y + b2v);
            *(float4*)&out[n * M_ + m0 + tm * 4] = o;
        }
    }
}

// ---------------- launch ----------------
extern "C" void kernel_launch(void* const* d_in, const int* in_sizes, int n_in,
                              void* d_out, int out_size) {
    const float* X  = (const float*)d_in[0];
    const int*   V  = (const int*)d_in[1];
    const int*   E  = (const int*)d_in[2];
    const float* W1 = (const float*)d_in[3];
    const float* b1 = (const float*)d_in[4];
    const float* W2 = (const float*)d_in[5];
    const float* b2 = (const float*)d_in[6];
    float* out = (float*)d_out;

    k_init<<<128, 256>>>();
    k_scatter<<<NNZ_ / 8, 256>>>(X, V, E);
    k_gemm<<<dim3(N_ / 64, H_ / 64, 2), 256>>>(X, W1, b1);
    k_main<<<dim3(M_ / 64, N_ / 64), 128>>>(W2, b2, out);
}

// round 3
// speedup vs baseline: 1.2274x; 1.0413x over previous
#include <cuda_runtime.h>

#define N_    1024
#define M_    1024
#define D_    128
#define NNZ_  32768
#define H_    256

typedef unsigned long long u64;

// ---------------- device scratch (no allocations allowed) ----------------
__device__ int   g_cnt[M_];
__device__ __align__(16) float g_sum[M_ * D_];     // raw scatter sums [m][d]
__device__ __align__(16) float g_hxT[H_ * N_];     // [h][n]
__device__ __align__(16) float g_hebT[H_ * M_];    // [h][m]  (includes /cnt and +b1)

// ---------------- small helpers ----------------
__device__ __forceinline__ u64 bcast2(float v) {
    u64 r;
    asm("mov.b64 %0, {%1, %1};" : "=l"(r) : "f"(v));
    return r;
}

__device__ __forceinline__ float2 unpack2(u64 v) {
    float lo, hi;
    asm("mov.b64 {%0, %1}, %2;" : "=f"(lo), "=f"(hi) : "l"(v));
    return make_float2(lo, hi);
}

// acc2 += relu(a2 + b2) * w2   (packed f32x2; relu on the scalar halves)
__device__ __forceinline__ void relu_fma2(u64 &acc, u64 a, u64 b, u64 w) {
    asm("{\n\t"
        ".reg .b64 t;\n\t"
        ".reg .f32 lo, hi;\n\t"
        "add.rn.f32x2 t, %1, %2;\n\t"
        "mov.b64 {lo, hi}, t;\n\t"
        "max.f32 lo, lo, 0f00000000;\n\t"
        "max.f32 hi, hi, 0f00000000;\n\t"
        "mov.b64 t, {lo, hi};\n\t"
        "fma.rn.f32x2 %0, t, %3, %0;\n\t"
        "}"
        : "+l"(acc) : "l"(a), "l"(b), "l"(w));
}

__device__ __forceinline__ float sigmoidf_fast(float x) {
    return 1.0f / (1.0f + __expf(-x));
}

// ---------------- stage 1: zero logits (d_out) + scratch ----------------
// grid 1024 x 256 : 262144 threads, one float4 of d_out each
__global__ void k_init(float* __restrict__ out) {
    int i = blockIdx.x * blockDim.x + threadIdx.x;
    float4 z = make_float4(0.f, 0.f, 0.f, 0.f);
    ((float4*)out)[i] = z;
    if (i < (M_ * D_) / 4) ((float4*)g_sum)[i] = z;
    if (i < M_) g_cnt[i] = 0;
}

// ---------------- stage 2: vector-atomic scatter ----------------
// one warp per edge; each lane reduces a float4 of the X row into g_sum[e]
__global__ __launch_bounds__(256) void k_scatter(const float* __restrict__ X,
                                                 const int* __restrict__ V,
                                                 const int* __restrict__ E) {
    int edge = blockIdx.x * 8 + (threadIdx.x >> 5);
    int lane = threadIdx.x & 31;
    int e = E[edge];
    int v = V[edge];
    float4 x = *(const float4*)&X[v * D_ + lane * 4];
    float* dst = &g_sum[e * D_ + lane * 4];
    asm volatile("red.global.add.v4.f32 [%0], {%1, %2, %3, %4};"
                 :: "l"(dst), "f"(x.x), "f"(x.y), "f"(x.z), "f"(x.w) : "memory");
    if (lane == 0) atomicAdd(&g_cnt[e], 1);
}

// ---------------- stage 3: the two small GEMMs (fused, transposed output) --
// z==0: outT = (X @ W1[:D]).T                       -> g_hxT[h][n]
// z==1: outT = ((g_sum @ W1[D:]) * rcp_cnt).T + b1  -> g_hebT[h][m]
__global__ __launch_bounds__(256) void k_gemm(const float* __restrict__ X,
                                              const float* __restrict__ W1,
                                              const float* __restrict__ b1) {
    int z = blockIdx.z;
    const float* A    = z ? g_sum  : X;
    float*       outT = z ? g_hebT : g_hxT;
    int dof = z ? D_ : 0;

    int n0 = blockIdx.x * 64;
    int h0 = blockIdx.y * 64;

    __shared__ float As[16][65];   // [dk][n]
    __shared__ float Ws[16][64];   // [dk][h]

    int tid = threadIdx.x;
    int tn  = tid & 15;   // n sub-tile (4 wide)
    int th  = tid >> 4;   // h sub-tile (4 wide)

    float acc[4][4];      // [n][h]
    #pragma unroll
    for (int i = 0; i < 4; i++)
        #pragma unroll
        for (int j = 0; j < 4; j++)
            acc[i][j] = 0.f;

    for (int d0 = 0; d0 < D_; d0 += 16) {
        #pragma unroll
        for (int r = 0; r < 4; r++) {
            int i  = r * 256 + tid;
            int dk = i & 15;
            int nl = i >> 4;
            As[dk][nl] = A[(n0 + nl) * D_ + d0 + dk];
        }
        #pragma unroll
        for (int r = 0; r < 4; r++) {
            int i  = r * 256 + tid;
            int hh = i & 63;
            int dk = i >> 6;
            Ws[dk][hh] = W1[(dof + d0 + dk) * H_ + h0 + hh];
        }
        __syncthreads();
        #pragma unroll
        for (int dk = 0; dk < 16; dk++) {
            float a[4], w[4];
            #pragma unroll
            for (int i = 0; i < 4; i++) a[i] = As[dk][tn * 4 + i];
            #pragma unroll
            for (int j = 0; j < 4; j++) w[j] = Ws[dk][th * 4 + j];
            #pragma unroll
            for (int i = 0; i < 4; i++)
                #pragma unroll
                for (int j = 0; j < 4; j++)
                    acc[i][j] = fmaf(a[i], w[j], acc[i][j]);
        }
        __syncthreads();
    }

    float scale[4] = {1.f, 1.f, 1.f, 1.f};
    if (z) {
        #pragma unroll
        for (int i = 0; i < 4; i++) {
            int c = g_cnt[n0 + tn * 4 + i];
            scale[i] = 1.0f / ((c > 0) ? (float)c : 1.0f);
        }
    }
    #pragma unroll
    for (int j = 0; j < 4; j++) {
        int h = h0 + th * 4 + j;
        float bb = z ? b1[h] : 0.f;
        float4 v = make_float4(acc[0][j] * scale[0] + bb,
                               acc[1][j] * scale[1] + bb,
                               acc[2][j] * scale[2] + bb,
                               acc[3][j] * scale[3] + bb);
        *(float4*)&outT[h * N_ + n0 + tn * 4] = v;
    }
}

// ---------------- stage 4: main N x M x H contraction (h-split) ----------
// grid (H/64, M/64, N/64) = 1024 blocks, 128 threads, single wave at 7/SM.
// Each block: 64x64 output tile x 64 h-values, partials red.add'ed to out.
// Thread: 4 n (scalar) x 8 m (4 f32x2 pairs, m-contiguous for vector RED).
__global__ __launch_bounds__(128, 7) void k_main(const float* __restrict__ W2,
                                                 float* __restrict__ out) {
    __shared__ __align__(16) float hx_s[32][64];
    __shared__ __align__(16) float heb_s[32][64];
    __shared__ float w2_s[64];

    int hb = blockIdx.x * 64;
    int m0 = blockIdx.y * 64;
    int n0 = blockIdx.z * 64;
    int tid = threadIdx.x;
    int tn  = tid & 15;   // n base = tn*4
    int tm  = tid >> 4;   // m base = tm*8

    u64 acc[4][4];        // [ni][mpair]
    #pragma unroll
    for (int i = 0; i < 4; i++)
        #pragma unroll
        for (int p = 0; p < 4; p++)
            acc[i][p] = 0ull;

    if (tid < 64) w2_s[tid] = W2[hb + tid];

    int cg = tid & 15;    // float4 column group for loads
    int r0 = tid >> 4;    // row base for loads (0..7)

    for (int sc = 0; sc < 2; sc++) {
        int hbase = hb + sc * 32;
        #pragma unroll
        for (int k = 0; k < 4; k++) {
            int hh = k * 8 + r0;
            *(float4*)&hx_s[hh][cg * 4]  = *(const float4*)&g_hxT[(hbase + hh) * N_ + n0 + cg * 4];
            *(float4*)&heb_s[hh][cg * 4] = *(const float4*)&g_hebT[(hbase + hh) * M_ + m0 + cg * 4];
        }
        __syncthreads();

        #pragma unroll 4
        for (int hh = 0; hh < 32; hh++) {
            float4 hx4 = *(const float4*)&hx_s[hh][tn * 4];
            ulonglong2 e0 = *(const ulonglong2*)&heb_s[hh][tm * 8];
            ulonglong2 e1 = *(const ulonglong2*)&heb_s[hh][tm * 8 + 4];
            u64 w2p = bcast2(w2_s[sc * 32 + hh]);
            u64 q0 = bcast2(hx4.x);
            u64 q1 = bcast2(hx4.y);
            u64 q2 = bcast2(hx4.z);
            u64 q3 = bcast2(hx4.w);

            relu_fma2(acc[0][0], e0.x, q0, w2p);
            relu_fma2(acc[0][1], e0.y, q0, w2p);
            relu_fma2(acc[0][2], e1.x, q0, w2p);
            relu_fma2(acc[0][3], e1.y, q0, w2p);

            relu_fma2(acc[1][0], e0.x, q1, w2p);
            relu_fma2(acc[1][1], e0.y, q1, w2p);
            relu_fma2(acc[1][2], e1.x, q1, w2p);
            relu_fma2(acc[1][3], e1.y, q1, w2p);

            relu_fma2(acc[2][0], e0.x, q2, w2p);
            relu_fma2(acc[2][1], e0.y, q2, w2p);
            relu_fma2(acc[2][2], e1.x, q2, w2p);
            relu_fma2(acc[2][3], e1.y, q2, w2p);

            relu_fma2(acc[3][0], e0.x, q3, w2p);
            relu_fma2(acc[3][1], e0.y, q3, w2p);
            relu_fma2(acc[3][2], e1.x, q3, w2p);
            relu_fma2(acc[3][3], e1.y, q3, w2p);
        }
        __syncthreads();
    }

    // epilogue: vector-RED partial logits into out[n][m]
    #pragma unroll
    for (int i = 0; i < 4; i++) {
        int n = n0 + tn * 4 + i;
        float2 a = unpack2(acc[i][0]);
        float2 b = unpack2(acc[i][1]);
        float2 c = unpack2(acc[i][2]);
        float2 d = unpack2(acc[i][3]);
        float* dst = &out[n * M_ + m0 + tm * 8];
        asm volatile("red.global.add.v4.f32 [%0], {%1, %2, %3, %4};"
                     :: "l"(dst), "f"(a.x), "f"(a.y), "f"(b.x), "f"(b.y) : "memory");
        asm volatile("red.global.add.v4.f32 [%0], {%1, %2, %3, %4};"
                     :: "l"(dst + 4), "f"(c.x), "f"(c.y), "f"(d.x), "f"(d.y) : "memory");
    }
}

// ---------------- stage 5: sigmoid epilogue (in place on d_out) ----------
__global__ void k_sig(float* __restrict__ out, const float* __restrict__ b2p) {
    int i = blockIdx.x * blockDim.x + threadIdx.x;
    float b2 = b2p[0];
    float4 v = ((float4*)out)[i];
    v.x = sigmoidf_fast(v.x + b2);
    v.y = sigmoidf_fast(v.y + b2);
    v.z = sigmoidf_fast(v.z + b2);
    v.w = sigmoidf_fast(v.w + b2);
    ((float4*)out)[i] = v;
}

// ---------------- launch ----------------
extern "C" void kernel_launch(void* const* d_in, const int* in_sizes, int n_in,
                              void* d_out, int out_size) {
    const float* X  = (const float*)d_in[0];
    const int*   V  = (const int*)d_in[1];
    const int*   E  = (const int*)d_in[2];
    const float* W1 = (const float*)d_in[3];
    const float* b1 = (const float*)d_in[4];
    const float* W2 = (const float*)d_in[5];
    const float* b2 = (const float*)d_in[6];
    float* out = (float*)d_out;

    k_init<<<1024, 256>>>(out);
    k_scatter<<<NNZ_ / 8, 256>>>(X, V, E);
    k_gemm<<<dim3(N_ / 64, H_ / 64, 2), 256>>>(X, W1, b1);
    k_main<<<dim3(H_ / 64, M_ / 64, N_ / 64), 128>>>(W2, out);
    k_sig<<<1024, 256>>>(out, b2);
}